// round 13
// baseline (speedup 1.0000x reference)
#include <cuda_runtime.h>
#include <cuda_fp16.h>
typedef unsigned int u32; typedef unsigned long long u64; typedef unsigned short u16;

#define HWp 4096
#define Cc  256
#define Dd  256
#define ZQ_SIZE (8*256*4096)
#define DIFF_OFF ZQ_SIZE
#define IND_OFF (ZQ_SIZE+1)
#define DELTA 0.04f
#define ZSTR 260   // z_s row stride in floats: 1040B, 16B-aligned for all rows

// ---- device scratch ----
__device__ uint4 g_Af[256*4096];   // A hi frags: per tile t: 4096 uint4 (64KB)
__device__ u64   g_Bh[8*8192];     // B hi frags: per chunk nc: 8192 u64 (64KB)

__device__ __forceinline__ u32 smem_u32(const void* p){u32 a;asm("{ .reg .u64 t; cvta.to.shared.u64 t, %1; cvt.u32.u64 %0, t; }":"=r"(a):"l"(p));return a;}
__device__ __forceinline__ u32 ordu(float v){u32 u=__float_as_uint(v);return (u&0x80000000u)?~u:(u|0x80000000u);}
__device__ __forceinline__ float unord(u32 u){return (u&0x80000000u)?__uint_as_float(u^0x80000000u):__uint_as_float(~u);}
__device__ __forceinline__ void hmma(float* c,const u32* a,const u32* b){
  asm volatile("mma.sync.aligned.m16n8k16.row.col.f32.f16.f16.f32 {%0,%1,%2,%3}, {%4,%5,%6,%7}, {%8,%9}, {%0,%1,%2,%3};"
    : "+f"(c[0]),"+f"(c[1]),"+f"(c[2]),"+f"(c[3])
    : "r"(a[0]),"r"(a[1]),"r"(a[2]),"r"(a[3]),"r"(b[0]),"r"(b[1]));
}
__device__ __forceinline__ void cpa16(u32 dst,const void* src){
  asm volatile("cp.async.cg.shared.global [%0], [%1], 16;"::"r"(dst),"l"(src):"memory");
}
#define CPA_COMMIT() asm volatile("cp.async.commit_group;":::"memory")
#define CPA_WAIT1()  asm volatile("cp.async.wait_group 1;":::"memory")
#define CPA_WAIT0()  asm volatile("cp.async.wait_group 0;":::"memory")

__device__ __forceinline__ u16 h16(float v){__half h=__float2half_rn(v);return *(u16*)&h;}

// ===================== K1 =====================
extern __shared__ float k1s[];
__global__ __launch_bounds__(256,1) void k1(const float* __restrict__ z,const float* __restrict__ pw){
  int tid=threadIdx.x, t=blockIdx.x;
  if(t<256){
    int pix0=t*128, b=pix0>>12, hw0=pix0&4095;
    const float* zb=z+(size_t)b*Cc*HWp+hw0;
    #pragma unroll
    for(int i=0;i<32;i++){
      int e4=tid+i*256; int c=e4>>5; int p4=(e4&31)<<2;
      float4 v=*(const float4*)(zb+(size_t)c*HWp+p4);
      float* d=k1s+c*129+p4;
      d[0]=v.x; d[1]=v.y; d[2]=v.z; d[3]=v.w;
    }
    __syncthreads();
    uint4* Ah=g_Af+(size_t)t*4096;
    #pragma unroll
    for(int i=0;i<16;i++){
      int u=tid+i*256;
      int lane=u&31, ks=(u>>5)&15, mt=u>>9;
      int r0=mt*16+(lane>>2);
      int c0=ks*16+((lane&3)<<1);
      u16 h0=h16(k1s[(c0  )*129+r0  ]*64.f), h1=h16(k1s[(c0+1)*129+r0  ]*64.f);
      u16 h2=h16(k1s[(c0  )*129+r0+8]*64.f), h3=h16(k1s[(c0+1)*129+r0+8]*64.f);
      u16 h4=h16(k1s[(c0+8)*129+r0  ]*64.f), h5=h16(k1s[(c0+9)*129+r0  ]*64.f);
      u16 h6=h16(k1s[(c0+8)*129+r0+8]*64.f), h7=h16(k1s[(c0+9)*129+r0+8]*64.f);
      uint4 H;
      H.x=h0|((u32)h1<<16); H.y=h2|((u32)h3<<16); H.z=h4|((u32)h5<<16); H.w=h6|((u32)h7<<16);
      Ah[u]=H;
    }
  } else {
    int base=(t-256)*2048;
    #pragma unroll
    for(int i=0;i<8;i++){
      int u=base+tid+i*256;
      int lane=u&31;
      int ks=(u>>5)&15;
      int nt=(u>>9)&15;
      int chunk=u>>13;
      int n=chunk*128+nt*8+(lane>>2);
      int k0=ks*16+((lane&3)<<1);
      const float* sp=pw+(size_t)n*Cc;
      u16 h0=h16(sp[k0  ]*32.f), h1=h16(sp[k0+1]*32.f);
      u16 h2=h16(sp[k0+8]*32.f), h3=h16(sp[k0+9]*32.f);
      g_Bh[(size_t)chunk*8192 + (nt*16+ks)*32 + lane]
        = (u64)(h0|((u32)h1<<16)) | ((u64)(h2|((u32)h3<<16))<<32);
    }
  }
}

// ===================== K2 =====================
// dyn smem (196608B):
//  MMA phase : A frags [0,65536); B buf0 [65536,131072); B buf1 [131072,196608)
//  post phase: z_s [128][ZSTR]f at [0,133120); worklist u32 at [133120,196608) -> 15872 entries
extern __shared__ char k2s[];
__global__ __launch_bounds__(512,1) void k2(const float* __restrict__ z,const float* __restrict__ pw,
                                            const float* __restrict__ pb,const float* __restrict__ emb,
                                            float* __restrict__ out){
  __shared__ u64 s_bx[128];
  __shared__ u32 s_best[128];
  __shared__ float s_pb[1024];
  __shared__ int s_idx[128];
  __shared__ int s_wcnt;
  int tid=threadIdx.x, lane=tid&31, warp=tid>>5, mw=warp&3, nw=warp>>2, t=blockIdx.x;
  int pix0=t*128, b=pix0>>12, hw0=pix0&4095;
  char* sm=k2s;
  u32 smb=smem_u32(k2s);
  float* z_s=(float*)sm;                   // [128][ZSTR] = 133120 B
  u32* s_wl=(u32*)(sm+133120);             // 15872 entries
  const int WMAX=15872;

  // group 0: A frags (64KB) + B chunk 0; group 1: B chunk 1
  { const char* As=(const char*)(g_Af+(size_t)t*4096);
    #pragma unroll
    for(int i=0;i<8;i++){int e=tid+i*512; cpa16(smb+e*16,As+(size_t)e*16);}
    const char* B0=(const char*)g_Bh;
    #pragma unroll
    for(int i=0;i<8;i++){int e=tid+i*512; cpa16(smb+65536+e*16,B0+(size_t)e*16);}
    CPA_COMMIT();
    const char* B1=(const char*)g_Bh+65536;
    #pragma unroll
    for(int i=0;i<8;i++){int e=tid+i*512; cpa16(smb+131072+e*16,B1+(size_t)e*16);}
    CPA_COMMIT();
  }
  for(int i=tid;i<1024;i+=512) s_pb[i]=pb[i];
  if(tid<128){ s_best[tid]=0u; s_bx[tid]=0ull; }
  if(tid==0) s_wcnt=0;

  float bestV[4], secV[4]; int bestI[4];
  #pragma unroll
  for(int i=0;i<4;i++){bestV[i]=-3.4e38f;secV[i]=-3.4e38f;bestI[i]=0;}
  const float inv=4.8828125e-4f;
  const uint4* Ahp=(const uint4*)sm;

  for(int nc=0;nc<8;nc++){
    CPA_WAIT1();
    __syncthreads();
    const char* Bst=sm+65536+(nc&1)*65536;
    float C[2][4][4];
    #pragma unroll
    for(int i=0;i<2;i++)
      #pragma unroll
      for(int j=0;j<4;j++)
        #pragma unroll
        for(int c=0;c<4;c++) C[i][j][c]=0.f;

    #pragma unroll
    for(int ks=0;ks<16;ks++){
      u32 ah[2][4];
      #pragma unroll
      for(int i=0;i<2;i++){
        uint4 va=Ahp[((mw*2+i)*16+ks)*32+lane];
        ah[i][0]=va.x; ah[i][1]=va.y; ah[i][2]=va.z; ah[i][3]=va.w;
      }
      u32 bh[4][2];
      #pragma unroll
      for(int j=0;j<4;j++){
        int nt=nw*4+j;
        uint2 vh=*(const uint2*)(Bst+(size_t)((nt*16+ks)*32+lane)*8);
        bh[j][0]=vh.x; bh[j][1]=vh.y;
      }
      #pragma unroll
      for(int i=0;i<2;i++)
        #pragma unroll
        for(int j=0;j<4;j++)
          hmma(C[i][j],ah[i],bh[j]);
    }

    int nb=nc*128+nw*32+((lane&3)<<1);
    #pragma unroll
    for(int i=0;i<2;i++)
      #pragma unroll
      for(int rr=0;rr<2;rr++){
        int r=i*2+rr;
        #pragma unroll
        for(int j=0;j<4;j++)
          #pragma unroll
          for(int cc=0;cc<2;cc++){
            int n=nb+j*8+cc;
            float val=C[i][j][rr*2+cc]*inv+s_pb[n];
            if(val>bestV[r]){secV[r]=bestV[r];bestV[r]=val;bestI[r]=n;}
            else if(val>secV[r]) secV[r]=val;
          }
      }
    __syncthreads();
    if(nc+2<8){
      u32 d=smb+65536+(nc&1)*65536;
      const char* s=(const char*)g_Bh+(size_t)(nc+2)*65536;
      #pragma unroll
      for(int j2=0;j2<8;j2++){int e=tid+j2*512; cpa16(d+e*16,s+(size_t)e*16);}
    }
    CPA_COMMIT();
  }
  CPA_WAIT0();

  // approx global max per pixel
  #pragma unroll
  for(int i=0;i<2;i++)
    #pragma unroll
    for(int rr=0;rr<2;rr++){
      int row=mw*32+i*16+rr*8+(lane>>2);
      atomicMax(&s_best[row],ordu(bestV[i*2+rr]));
    }
  __syncthreads();   // A/B buffers dead from here; s_best final

  // build worklist — best pushed directly; sec expands its 64-n subset
  #pragma unroll
  for(int i=0;i<2;i++)
    #pragma unroll
    for(int rr=0;rr<2;rr++){
      int r=i*2+rr;
      int row=mw*32+i*16+rr*8+(lane>>2);
      float thr=unord(s_best[row])-DELTA;
      if(bestV[r]>=thr){
        int sl=atomicAdd(&s_wcnt,1);
        if(sl<WMAX) s_wl[sl]=((u32)row<<10)|(u32)bestI[r];
      }
      if(secV[r]>=thr){
        int base2=atomicAdd(&s_wcnt,64);
        int q=lane&3, k2i=0;
        for(int nc2=0;nc2<8;nc2++)
          for(int j=0;j<4;j++)
            #pragma unroll
            for(int cc=0;cc<2;cc++){
              int n=nc2*128+nw*32+j*8+q*2+cc;
              if(base2+k2i<WMAX) s_wl[base2+k2i]=((u32)row<<10)|(u32)n;
              k2i++;
            }
      }
    }

  // stage z tile into smem as [p][c] (stride ZSTR) — coalesced global reads
  { const float* zb=z+(size_t)b*Cc*HWp+hw0;
    #pragma unroll
    for(int i=0;i<16;i++){
      int e4=tid+i*512; int c=e4>>5; int p4=(e4&31)<<2;
      float4 v=*(const float4*)(zb+(size_t)c*HWp+p4);
      z_s[(p4+0)*ZSTR+c]=v.x; z_s[(p4+1)*ZSTR+c]=v.y;
      z_s[(p4+2)*ZSTR+c]=v.z; z_s[(p4+3)*ZSTR+c]=v.w;
    }
  }
  __syncthreads();

  int cnt=s_wcnt;
  if(cnt<=WMAX){
    // exact rescore: half-warp per entry, all warps share the worklist
    int half=lane>>4, hl=lane&15;
    for(int e0=warp*2;e0<cnt;e0+=32){
      int e=e0+half;
      u32 ent=s_wl[(e<cnt)?e:e0];
      int p=(int)(ent>>10), n=(int)(ent&1023);
      const float* zr=z_s+p*ZSTR+hl*16;
      const float* wr=pw+(size_t)n*Cc+hl*16;
      float s=0.f;
      #pragma unroll
      for(int q4=0;q4<4;q4++){
        float4 zv=*(const float4*)(zr+q4*4);
        float4 wv=*(const float4*)(wr+q4*4);
        s=fmaf(zv.x,wv.x,s); s=fmaf(zv.y,wv.y,s);
        s=fmaf(zv.z,wv.z,s); s=fmaf(zv.w,wv.w,s);
      }
      #pragma unroll
      for(int o=8;o>=1;o>>=1) s+=__shfl_xor_sync(0xffffffffu,s,o);
      if(hl==0&&e<cnt){
        float v=s+s_pb[n];
        u64 key=((u64)ordu(v)<<32)|(u32)(1023-n);
        atomicMax(&s_bx[p],key);
      }
    }
  }else{
    // unconditional-correctness fallback (practically never taken): full exact scan
    int half=lane>>4, hl=lane&15;
    for(int p=warp;p<128;p+=16){
      for(int n0=0;n0<1024;n0+=2){
        int n=n0+half;
        const float* zr=z_s+p*ZSTR+hl*16;
        const float* wr=pw+(size_t)n*Cc+hl*16;
        float s=0.f;
        #pragma unroll
        for(int q4=0;q4<4;q4++){
          float4 zv=*(const float4*)(zr+q4*4);
          float4 wv=*(const float4*)(wr+q4*4);
          s=fmaf(zv.x,wv.x,s); s=fmaf(zv.y,wv.y,s);
          s=fmaf(zv.z,wv.z,s); s=fmaf(zv.w,wv.w,s);
        }
        #pragma unroll
        for(int o=8;o>=1;o>>=1) s+=__shfl_xor_sync(0xffffffffu,s,o);
        if(hl==0){
          float v=s+s_pb[n];
          u64 key=((u64)ordu(v)<<32)|(u32)(1023-n);
          atomicMax(&s_bx[p],key);
        }
      }
    }
  }
  __syncthreads();

  if(tid<128){
    int idx=1023-(int)(s_bx[tid]&0xffffffffull);
    s_idx[tid]=idx;
    out[IND_OFF+pix0+tid]=(float)idx;
  }
  if(t==0&&tid==0) out[DIFF_OFF]=0.0f;
  __syncthreads();

  // gather epilogue (reuse z_s region, scalar stores)
  float* gs2=z_s;
  for(int i=tid;i<8192;i+=512){
    int p=i>>6; int d4=(i&63)<<2;
    float4 v=*(const float4*)(emb+(size_t)s_idx[p]*Dd+d4);
    float* d=gs2+p*ZSTR+d4;
    d[0]=v.x; d[1]=v.y; d[2]=v.z; d[3]=v.w;
  }
  __syncthreads();
  float* outz=out+(size_t)b*Dd*HWp+hw0;
  for(int i=tid;i<32768;i+=512){
    int d=i>>7, p=i&127;
    outz[(size_t)d*HWp+p]=gs2[p*ZSTR+d];
  }
}

extern "C" void kernel_launch(void* const* d_in, const int* in_sizes, int n_in,
                              void* d_out, int out_size)
{
  const float* z  =(const float*)d_in[0];
  const float* pw =(const float*)d_in[1];
  const float* pb =(const float*)d_in[2];
  const float* emb=(const float*)d_in[3];
  float* out=(float*)d_out;
  cudaFuncSetAttribute(k1,cudaFuncAttributeMaxDynamicSharedMemorySize,132096);
  cudaFuncSetAttribute(k2,cudaFuncAttributeMaxDynamicSharedMemorySize,196608);
  k1<<<288,256,132096>>>(z,pw);
  k2<<<256,512,196608>>>(z,pw,pb,emb,out);
}

// round 14
// speedup vs baseline: 1.1262x; 1.1262x over previous
#include <cuda_runtime.h>
#include <cuda_fp16.h>
typedef unsigned int u32; typedef unsigned long long u64; typedef unsigned short u16;

#define HWp 4096
#define Cc  256
#define Dd  256
#define ZQ_SIZE (8*256*4096)
#define DIFF_OFF ZQ_SIZE
#define IND_OFF (ZQ_SIZE+1)
#define DELTA 0.05f

// ---- device scratch ----
__device__ uint4 g_Af[256*4096];   // A hi frags: per tile t: 4096 uint4 (64KB)
__device__ u64   g_Bh[8*8192];     // B hi frags: per chunk nc: 8192 u64 (64KB)
__device__ float g_zt[32768*256];  // fp32 z, pixel-major (for exact rescore)

__device__ __forceinline__ u32 ordu(float v){u32 u=__float_as_uint(v);return (u&0x80000000u)?~u:(u|0x80000000u);}
__device__ __forceinline__ float unord(u32 u){return (u&0x80000000u)?__uint_as_float(u^0x80000000u):__uint_as_float(~u);}
__device__ __forceinline__ void hmma(float* c,const u32* a,const u32* b){
  asm volatile("mma.sync.aligned.m16n8k16.row.col.f32.f16.f16.f32 {%0,%1,%2,%3}, {%4,%5,%6,%7}, {%8,%9}, {%0,%1,%2,%3};"
    : "+f"(c[0]),"+f"(c[1]),"+f"(c[2]),"+f"(c[3])
    : "r"(a[0]),"r"(a[1]),"r"(a[2]),"r"(a[3]),"r"(b[0]),"r"(b[1]));
}
__device__ __forceinline__ u16 h16(float v){__half h=__float2half_rn(v);return *(u16*)&h;}

// exact fp32 warp dot: zv[8] per lane vs pw row n; deterministic xor-tree reduce
__device__ __forceinline__ float wdot(const float* zv,const float* __restrict__ pw,int n){
  const float* wr=pw+(size_t)n*Cc+(threadIdx.x&31)*8;
  float4 w0=*(const float4*)wr, w1=*(const float4*)(wr+4);
  float s=zv[0]*w0.x;
  s=fmaf(zv[1],w0.y,s); s=fmaf(zv[2],w0.z,s); s=fmaf(zv[3],w0.w,s);
  s=fmaf(zv[4],w1.x,s); s=fmaf(zv[5],w1.y,s); s=fmaf(zv[6],w1.z,s); s=fmaf(zv[7],w1.w,s);
  #pragma unroll
  for(int o=16;o>=1;o>>=1) s+=__shfl_xor_sync(0xffffffffu,s,o);
  return s;
}

// ===================== K1 (verbatim R8) =====================
extern __shared__ float k1s[];
__global__ __launch_bounds__(256,1) void k1(const float* __restrict__ z,const float* __restrict__ pw){
  int tid=threadIdx.x, t=blockIdx.x;
  if(t<256){
    int pix0=t*128, b=pix0>>12, hw0=pix0&4095;
    const float* zb=z+(size_t)b*Cc*HWp+hw0;
    #pragma unroll
    for(int i=0;i<32;i++){
      int e4=tid+i*256; int c=e4>>5; int p4=(e4&31)<<2;
      float4 v=*(const float4*)(zb+(size_t)c*HWp+p4);
      float* d=k1s+c*129+p4;
      d[0]=v.x; d[1]=v.y; d[2]=v.z; d[3]=v.w;
    }
    __syncthreads();
    #pragma unroll 8
    for(int i=0;i<128;i++) g_zt[(size_t)(pix0+i)*Cc+tid]=k1s[tid*129+i];
    uint4* Ah=g_Af+(size_t)t*4096;
    #pragma unroll
    for(int i=0;i<16;i++){
      int u=tid+i*256;
      int lane=u&31, ks=(u>>5)&15, mt=u>>9;
      int r0=mt*16+(lane>>2);
      int c0=ks*16+((lane&3)<<1);
      u16 h0=h16(k1s[(c0  )*129+r0  ]*64.f), h1=h16(k1s[(c0+1)*129+r0  ]*64.f);
      u16 h2=h16(k1s[(c0  )*129+r0+8]*64.f), h3=h16(k1s[(c0+1)*129+r0+8]*64.f);
      u16 h4=h16(k1s[(c0+8)*129+r0  ]*64.f), h5=h16(k1s[(c0+9)*129+r0  ]*64.f);
      u16 h6=h16(k1s[(c0+8)*129+r0+8]*64.f), h7=h16(k1s[(c0+9)*129+r0+8]*64.f);
      uint4 H;
      H.x=h0|((u32)h1<<16); H.y=h2|((u32)h3<<16); H.z=h4|((u32)h5<<16); H.w=h6|((u32)h7<<16);
      Ah[u]=H;
    }
  } else {
    int base=(t-256)*2048;
    #pragma unroll
    for(int i=0;i<8;i++){
      int u=base+tid+i*256;
      int lane=u&31;
      int ks=(u>>5)&15;
      int nt=(u>>9)&15;
      int chunk=u>>13;
      int n=chunk*128+nt*8+(lane>>2);
      int k0=ks*16+((lane&3)<<1);
      const float* sp=pw+(size_t)n*Cc;
      u16 h0=h16(sp[k0  ]*32.f), h1=h16(sp[k0+1]*32.f);
      u16 h2=h16(sp[k0+8]*32.f), h3=h16(sp[k0+9]*32.f);
      g_Bh[(size_t)chunk*8192 + (nt*16+ks)*32 + lane]
        = (u64)(h0|((u32)h1<<16)) | ((u64)(h2|((u32)h3<<16))<<32);
    }
  }
}

// ===================== K2: barrier-free main loop (B from L2) =====================
// dyn smem 131584B: A frags in [0,65536) during loop; epilogue staging [128][257] floats reuses all
extern __shared__ char k2s[];
__global__ __launch_bounds__(512,1) void k2(const float* __restrict__ pw,const float* __restrict__ pb,
                                            const float* __restrict__ emb,float* __restrict__ out){
  __shared__ u32 s_best[128];
  __shared__ float s_pb[1024];
  __shared__ int s_idx[128];
  __shared__ int s_cnt[128];
  __shared__ u32 s_cand[128][32];
  int tid=threadIdx.x, lane=tid&31, warp=tid>>5, mw=warp&3, nw=warp>>2, t=blockIdx.x;
  int pix0=t*128, b=pix0>>12, hw0=pix0&4095;
  char* sm=k2s;

  // load A hi frags (64KB) into smem (plain loads, one barrier)
  { const uint4* src=g_Af+(size_t)t*4096;
    uint4* dst=(uint4*)sm;
    #pragma unroll
    for(int i=0;i<8;i++) dst[tid+i*512]=src[tid+i*512];
  }
  for(int i=tid;i<1024;i+=512) s_pb[i]=pb[i];
  if(tid<128){ s_best[tid]=0u; s_cnt[tid]=0; }
  __syncthreads();

  float bestV[4], secV[4]; int bestI[4];
  #pragma unroll
  for(int i=0;i<4;i++){bestV[i]=-3.4e38f;secV[i]=-3.4e38f;bestI[i]=0;}
  const float inv=4.8828125e-4f;
  const uint4* Ahp=(const uint4*)sm;

  for(int nc=0;nc<8;nc++){
    const uint2* Bg=(const uint2*)(g_Bh+(size_t)nc*8192);
    float C[2][4][4];
    #pragma unroll
    for(int i=0;i<2;i++)
      #pragma unroll
      for(int j=0;j<4;j++)
        #pragma unroll
        for(int c=0;c<4;c++) C[i][j][c]=0.f;

    #pragma unroll
    for(int ks=0;ks<16;ks++){
      u32 bh[4][2];
      #pragma unroll
      for(int j=0;j<4;j++){
        int nt=nw*4+j;
        uint2 vh=__ldg(&Bg[(nt*16+ks)*32+lane]);   // coalesced 256B per (nt,ks), L2-resident
        bh[j][0]=vh.x; bh[j][1]=vh.y;
      }
      u32 ah[2][4];
      #pragma unroll
      for(int i=0;i<2;i++){
        uint4 va=Ahp[((mw*2+i)*16+ks)*32+lane];
        ah[i][0]=va.x; ah[i][1]=va.y; ah[i][2]=va.z; ah[i][3]=va.w;
      }
      #pragma unroll
      for(int i=0;i<2;i++)
        #pragma unroll
        for(int j=0;j<4;j++)
          hmma(C[i][j],ah[i],bh[j]);
    }

    // per-chunk top-2 tracking (R8 verbatim)
    int nb=nc*128+nw*32+((lane&3)<<1);
    #pragma unroll
    for(int i=0;i<2;i++)
      #pragma unroll
      for(int rr=0;rr<2;rr++){
        int r=i*2+rr;
        #pragma unroll
        for(int j=0;j<4;j++)
          #pragma unroll
          for(int cc=0;cc<2;cc++){
            int n=nb+j*8+cc;
            float val=C[i][j][rr*2+cc]*inv+s_pb[n];
            if(val>bestV[r]){secV[r]=bestV[r];bestV[r]=val;bestI[r]=n;}
            else if(val>secV[r]) secV[r]=val;
          }
      }
  }

  // approx global max per pixel (R8 verbatim)
  #pragma unroll
  for(int i=0;i<2;i++)
    #pragma unroll
    for(int rr=0;rr<2;rr++){
      int row=mw*32+i*16+rr*8+(lane>>2);
      atomicMax(&s_best[row],ordu(bestV[i*2+rr]));
    }
  __syncthreads();

  // candidate append (R8 verbatim)
  #pragma unroll
  for(int i=0;i<2;i++)
    #pragma unroll
    for(int rr=0;rr<2;rr++){
      int r=i*2+rr;
      int row=mw*32+i*16+rr*8+(lane>>2);
      float thr=unord(s_best[row])-DELTA;
      if(bestV[r]>=thr){
        int slot=atomicAdd(&s_cnt[row],1);
        s_cand[row][slot]=(u32)bestI[r];
      }
      if(secV[r]>=thr){
        int slot=atomicAdd(&s_cnt[row],1);
        s_cand[row][slot]=0x8000u|((u32)nw<<2)|(u32)(lane&3);
      }
    }
  __syncthreads();

  // exact rescore: one warp per pixel (R8 verbatim, z from g_zt)
  for(int p=warp;p<128;p+=16){
    const float* zr=g_zt+(size_t)(pix0+p)*Cc+lane*8;
    float4 z0=*(const float4*)zr, z1=*(const float4*)(zr+4);
    float zv[8]={z0.x,z0.y,z0.z,z0.w,z1.x,z1.y,z1.z,z1.w};
    float bv=-3.4e38f; int bi=1024;
    int cnt=s_cnt[p];
    for(int e=0;e<cnt;e++){
      u32 ent=s_cand[p][e];
      if(ent<0x8000u){
        int n=(int)ent;
        float v=wdot(zv,pw,n)+s_pb[n];
        if(v>bv||(v==bv&&n<bi)){bv=v;bi=n;}
      }else{
        int nwm=(int)((ent>>2)&3), q=(int)(ent&3);
        for(int nc2=0;nc2<8;nc2++)
          for(int j=0;j<4;j++)
            #pragma unroll
            for(int cc=0;cc<2;cc++){
              int n=nc2*128+nwm*32+j*8+q*2+cc;
              float v=wdot(zv,pw,n)+s_pb[n];
              if(v>bv||(v==bv&&n<bi)){bv=v;bi=n;}
            }
      }
    }
    if(lane==0){ s_idx[p]=bi; out[IND_OFF+pix0+p]=(float)bi; }
  }
  if(t==0&&tid==0) out[DIFF_OFF]=0.0f;
  __syncthreads();

  // gather epilogue (R8 verbatim)
  float* gs2=(float*)sm;           // [128][257] = 131584B = dyn smem
  for(int i=tid;i<8192;i+=512){
    int p=i>>6; int d4=(i&63)<<2;
    float4 v=*(const float4*)(emb+(size_t)s_idx[p]*Dd+d4);
    float* d=gs2+p*257+d4;
    d[0]=v.x; d[1]=v.y; d[2]=v.z; d[3]=v.w;
  }
  __syncthreads();
  float* outz=out+(size_t)b*Dd*HWp+hw0;
  for(int i=tid;i<32768;i+=512){
    int d=i>>7, p=i&127;
    outz[(size_t)d*HWp+p]=gs2[p*257+d];
  }
}

extern "C" void kernel_launch(void* const* d_in, const int* in_sizes, int n_in,
                              void* d_out, int out_size)
{
  const float* z  =(const float*)d_in[0];
  const float* pw =(const float*)d_in[1];
  const float* pb =(const float*)d_in[2];
  const float* emb=(const float*)d_in[3];
  float* out=(float*)d_out;
  cudaFuncSetAttribute(k1,cudaFuncAttributeMaxDynamicSharedMemorySize,132096);
  cudaFuncSetAttribute(k2,cudaFuncAttributeMaxDynamicSharedMemorySize,131584);
  k1<<<288,256,132096>>>(z,pw);
  k2<<<256,512,131584>>>(pw,pb,emb,out);
}

// round 15
// speedup vs baseline: 1.7519x; 1.5555x over previous
#include <cuda_runtime.h>
#include <cuda_fp16.h>
typedef unsigned int u32; typedef unsigned long long u64; typedef unsigned short u16;

#define HWp 4096
#define Cc  256
#define Dd  256
#define ZQ_SIZE (8*256*4096)
#define DIFF_OFF ZQ_SIZE
#define IND_OFF (ZQ_SIZE+1)
#define DELTA 0.05f

// ---- device scratch ----
__device__ uint4 g_Af[256*4096];   // A hi frags: per tile t: 4096 uint4 (64KB)
__device__ u64   g_Bh[8*8192];     // B hi frags: per chunk nc: 8192 u64 (64KB)
__device__ float g_zt[32768*256];  // fp32 z, pixel-major

__device__ __forceinline__ u32 smem_u32(const void* p){u32 a;asm("{ .reg .u64 t; cvta.to.shared.u64 t, %1; cvt.u32.u64 %0, t; }":"=r"(a):"l"(p));return a;}
__device__ __forceinline__ u32 ordu(float v){u32 u=__float_as_uint(v);return (u&0x80000000u)?~u:(u|0x80000000u);}
__device__ __forceinline__ float unord(u32 u){return (u&0x80000000u)?__uint_as_float(u^0x80000000u):__uint_as_float(~u);}
__device__ __forceinline__ void hmma(float* c,const u32* a,const u32* b){
  asm volatile("mma.sync.aligned.m16n8k16.row.col.f32.f16.f16.f32 {%0,%1,%2,%3}, {%4,%5,%6,%7}, {%8,%9}, {%0,%1,%2,%3};"
    : "+f"(c[0]),"+f"(c[1]),"+f"(c[2]),"+f"(c[3])
    : "r"(a[0]),"r"(a[1]),"r"(a[2]),"r"(a[3]),"r"(b[0]),"r"(b[1]));
}
__device__ __forceinline__ void cpa16(u32 dst,const void* src){
  asm volatile("cp.async.cg.shared.global [%0], [%1], 16;"::"r"(dst),"l"(src):"memory");
}
#define CPA_COMMIT() asm volatile("cp.async.commit_group;":::"memory")
#define CPA_WAIT1()  asm volatile("cp.async.wait_group 1;":::"memory")
#define CPA_WAIT0()  asm volatile("cp.async.wait_group 0;":::"memory")

__device__ __forceinline__ u16 h16(float v){__half h=__float2half_rn(v);return *(u16*)&h;}

// exact fp32 warp dot: zv[8] per lane vs pw row n; deterministic xor-tree reduce
__device__ __forceinline__ float wdot(const float* zv,const float* __restrict__ pw,int n){
  const float* wr=pw+(size_t)n*Cc+(threadIdx.x&31)*8;
  float4 w0=*(const float4*)wr, w1=*(const float4*)(wr+4);
  float s=zv[0]*w0.x;
  s=fmaf(zv[1],w0.y,s); s=fmaf(zv[2],w0.z,s); s=fmaf(zv[3],w0.w,s);
  s=fmaf(zv[4],w1.x,s); s=fmaf(zv[5],w1.y,s); s=fmaf(zv[6],w1.z,s); s=fmaf(zv[7],w1.w,s);
  #pragma unroll
  for(int o=16;o>=1;o>>=1) s+=__shfl_xor_sync(0xffffffffu,s,o);
  return s;
}

// ===================== K1 =====================
extern __shared__ float k1s[];
__global__ __launch_bounds__(256,1) void k1(const float* __restrict__ z,const float* __restrict__ pw){
  int tid=threadIdx.x, t=blockIdx.x;
  if(t<256){
    int pix0=t*128, b=pix0>>12, hw0=pix0&4095;
    const float* zb=z+(size_t)b*Cc*HWp+hw0;
    #pragma unroll
    for(int i=0;i<32;i++){
      int e4=tid+i*256; int c=e4>>5; int p4=(e4&31)<<2;
      float4 v=*(const float4*)(zb+(size_t)c*HWp+p4);
      float* d=k1s+c*129+p4;
      d[0]=v.x; d[1]=v.y; d[2]=v.z; d[3]=v.w;
    }
    __syncthreads();
    #pragma unroll 8
    for(int i=0;i<128;i++) g_zt[(size_t)(pix0+i)*Cc+tid]=k1s[tid*129+i];
    uint4* Ah=g_Af+(size_t)t*4096;
    #pragma unroll
    for(int i=0;i<16;i++){
      int u=tid+i*256;
      int lane=u&31, ks=(u>>5)&15, mt=u>>9;
      int r0=mt*16+(lane>>2);
      int c0=ks*16+((lane&3)<<1);
      u16 h0=h16(k1s[(c0  )*129+r0  ]*64.f), h1=h16(k1s[(c0+1)*129+r0  ]*64.f);
      u16 h2=h16(k1s[(c0  )*129+r0+8]*64.f), h3=h16(k1s[(c0+1)*129+r0+8]*64.f);
      u16 h4=h16(k1s[(c0+8)*129+r0  ]*64.f), h5=h16(k1s[(c0+9)*129+r0  ]*64.f);
      u16 h6=h16(k1s[(c0+8)*129+r0+8]*64.f), h7=h16(k1s[(c0+9)*129+r0+8]*64.f);
      uint4 H;
      H.x=h0|((u32)h1<<16); H.y=h2|((u32)h3<<16); H.z=h4|((u32)h5<<16); H.w=h6|((u32)h7<<16);
      Ah[u]=H;
    }
  } else {
    int base=(t-256)*2048;
    #pragma unroll
    for(int i=0;i<8;i++){
      int u=base+tid+i*256;
      int lane=u&31;
      int ks=(u>>5)&15;
      int nt=(u>>9)&15;
      int chunk=u>>13;
      int n=chunk*128+nt*8+(lane>>2);
      int k0=ks*16+((lane&3)<<1);
      const float* sp=pw+(size_t)n*Cc;
      u16 h0=h16(sp[k0  ]*32.f), h1=h16(sp[k0+1]*32.f);
      u16 h2=h16(sp[k0+8]*32.f), h3=h16(sp[k0+9]*32.f);
      g_Bh[(size_t)chunk*8192 + (nt*16+ks)*32 + lane]
        = (u64)(h0|((u32)h1<<16)) | ((u64)(h2|((u32)h3<<16))<<32);
    }
  }
}

// ===================== K2 =====================
// dyn smem: A hi 64KB [0,65536); B buf0 [65536,+65536); B buf1 [131072,+65536) = 196608
extern __shared__ char k2s[];
__global__ __launch_bounds__(512,1) void k2(const float* __restrict__ z,const float* __restrict__ pw,
                                            const float* __restrict__ pb,const float* __restrict__ emb,
                                            float* __restrict__ out){
  __shared__ u32 s_best[128];
  __shared__ float s_pb[1024];
  __shared__ int s_idx[128];
  __shared__ int s_cnt[128];
  __shared__ u16 s_cand[128][32];
  int tid=threadIdx.x, lane=tid&31, warp=tid>>5, mw=warp&3, nw=warp>>2, t=blockIdx.x;
  int pix0=t*128, b=pix0>>12, hw0=pix0&4095;
  char* sm=k2s;
  u32 smb=smem_u32(k2s);

  { const uint4* src=g_Af+(size_t)t*4096; uint4* dst=(uint4*)sm;
    #pragma unroll
    for(int i=0;i<8;i++) dst[tid+i*512]=src[tid+i*512]; }
  for(int i=tid;i<1024;i+=512) s_pb[i]=pb[i];
  if(tid<128){ s_best[tid]=0u; s_cnt[tid]=0; }
  __syncthreads();

  #pragma unroll
  for(int c2=0;c2<2;c2++){
    u32 d=smb+65536+c2*65536;
    const char* s=(const char*)g_Bh+(size_t)c2*65536;
    #pragma unroll
    for(int j2=0;j2<8;j2++){int e=tid+j2*512; cpa16(d+e*16,s+(size_t)e*16);}
    CPA_COMMIT();
  }

  float bestV[4], secV[4]; int bestI[4];
  #pragma unroll
  for(int i=0;i<4;i++){bestV[i]=-3.4e38f;secV[i]=-3.4e38f;bestI[i]=0;}
  const float inv=4.8828125e-4f;
  const uint4* Ahp=(const uint4*)sm;

  for(int nc=0;nc<8;nc++){
    CPA_WAIT1();
    __syncthreads();
    const char* Bst=sm+65536+(nc&1)*65536;
    float C[2][4][4];
    #pragma unroll
    for(int i=0;i<2;i++)
      #pragma unroll
      for(int j=0;j<4;j++)
        #pragma unroll
        for(int c=0;c<4;c++) C[i][j][c]=0.f;

    #pragma unroll
    for(int ks=0;ks<16;ks++){
      u32 ah[2][4];
      #pragma unroll
      for(int i=0;i<2;i++){
        uint4 va=Ahp[((mw*2+i)*16+ks)*32+lane];
        ah[i][0]=va.x; ah[i][1]=va.y; ah[i][2]=va.z; ah[i][3]=va.w;
      }
      u32 bh[4][2];
      #pragma unroll
      for(int j=0;j<4;j++){
        int nt=nw*4+j;
        uint2 vh=*(const uint2*)(Bst+(size_t)((nt*16+ks)*32+lane)*8);
        bh[j][0]=vh.x; bh[j][1]=vh.y;
      }
      #pragma unroll
      for(int i=0;i<2;i++)
        #pragma unroll
        for(int j=0;j<4;j++)
          hmma(C[i][j],ah[i],bh[j]);
    }

    int nb=nc*128+nw*32+((lane&3)<<1);
    #pragma unroll
    for(int i=0;i<2;i++)
      #pragma unroll
      for(int rr=0;rr<2;rr++){
        int r=i*2+rr;
        #pragma unroll
        for(int j=0;j<4;j++)
          #pragma unroll
          for(int cc=0;cc<2;cc++){
            int n=nb+j*8+cc;
            float val=C[i][j][rr*2+cc]*inv+s_pb[n];
            if(val>bestV[r]){secV[r]=bestV[r];bestV[r]=val;bestI[r]=n;}
            else if(val>secV[r]) secV[r]=val;
          }
      }
    __syncthreads();
    if(nc+2<8){
      u32 d=smb+65536+(nc&1)*65536;
      const char* s=(const char*)g_Bh+(size_t)(nc+2)*65536;
      #pragma unroll
      for(int j2=0;j2<8;j2++){int e=tid+j2*512; cpa16(d+e*16,s+(size_t)e*16);}
    }
    CPA_COMMIT();
  }
  CPA_WAIT0();

  #pragma unroll
  for(int i=0;i<2;i++)
    #pragma unroll
    for(int rr=0;rr<2;rr++){
      int row=mw*32+i*16+rr*8+(lane>>2);
      atomicMax(&s_best[row],ordu(bestV[i*2+rr]));
    }
  __syncthreads();

  #pragma unroll
  for(int i=0;i<2;i++)
    #pragma unroll
    for(int rr=0;rr<2;rr++){
      int r=i*2+rr;
      int row=mw*32+i*16+rr*8+(lane>>2);
      float thr=unord(s_best[row])-DELTA;
      if(bestV[r]>=thr){
        int slot=atomicAdd(&s_cnt[row],1);
        s_cand[row][slot]=(u16)bestI[r];
      }
      if(secV[r]>=thr){
        int slot=atomicAdd(&s_cnt[row],1);
        s_cand[row][slot]=(u16)(0x8000u|((u32)nw<<2)|(u32)(lane&3));
      }
    }
  __syncthreads();

  // exact rescore: one warp per pixel
  for(int p=warp;p<128;p+=16){
    const float* zr=g_zt+(size_t)(pix0+p)*Cc+lane*8;
    float4 z0=*(const float4*)zr, z1=*(const float4*)(zr+4);
    float zv[8]={z0.x,z0.y,z0.z,z0.w,z1.x,z1.y,z1.z,z1.w};
    float bv=-3.4e38f; int bi=1024;
    int cnt=s_cnt[p];
    for(int e=0;e<cnt;e++){
      u32 ent=s_cand[p][e];
      if(ent<0x8000u){
        int n=(int)ent;
        float v=wdot(zv,pw,n)+s_pb[n];
        if(v>bv||(v==bv&&n<bi)){bv=v;bi=n;}
      }else{
        int nwm=(int)((ent>>2)&3), q=(int)(ent&3);
        for(int nc2=0;nc2<8;nc2++)
          for(int j=0;j<4;j++)
            #pragma unroll
            for(int cc=0;cc<2;cc++){
              int n=nc2*128+nwm*32+j*8+q*2+cc;
              float v=wdot(zv,pw,n)+s_pb[n];
              if(v>bv||(v==bv&&n<bi)){bv=v;bi=n;}
            }
      }
    }
    if(lane==0){ s_idx[p]=bi; out[IND_OFF+pix0+p]=(float)bi; }
  }
  if(t==0&&tid==0) out[DIFF_OFF]=0.0f;
  __syncthreads();

  // gather epilogue
  float* gs2=(float*)sm;           // [128][257] = 131584B < 196608
  for(int i=tid;i<8192;i+=512){
    int p=i>>6; int d4=(i&63)<<2;
    float4 v=*(const float4*)(emb+(size_t)s_idx[p]*Dd+d4);
    float* d=gs2+p*257+d4;
    d[0]=v.x; d[1]=v.y; d[2]=v.z; d[3]=v.w;
  }
  __syncthreads();
  float* outz=out+(size_t)b*Dd*HWp+hw0;
  for(int i=tid;i<32768;i+=512){
    int d=i>>7, p=i&127;
    outz[(size_t)d*HWp+p]=gs2[p*257+d];
  }
}

extern "C" void kernel_launch(void* const* d_in, const int* in_sizes, int n_in,
                              void* d_out, int out_size)
{
  const float* z  =(const float*)d_in[0];
  const float* pw =(const float*)d_in[1];
  const float* pb =(const float*)d_in[2];
  const float* emb=(const float*)d_in[3];
  float* out=(float*)d_out;
  cudaFuncSetAttribute(k1,cudaFuncAttributeMaxDynamicSharedMemorySize,132096);
  cudaFuncSetAttribute(k2,cudaFuncAttributeMaxDynamicSharedMemorySize,196608);
  k1<<<288,256,132096>>>(z,pw);
  k2<<<256,512,196608>>>(z,pw,pb,emb,out);
}